// round 3
// baseline (speedup 1.0000x reference)
#include <cuda_runtime.h>
#include <cstdint>
#include <math_constants.h>

#define CD    256
#define NPIX  65536
#define NCODE 1024
#define PATCH 48

// ---------------- device scratch (no allocs allowed) ----------------
__device__ float g_Wcomb[PATCH*CD];     // [p][c] combined encoder+conv1 weight
__device__ float g_bcomb[CD];
__device__ float g_cnorm[NCODE];        // C = ||c||^2  (full, not half)
__device__ float g_cb2[NCODE*CD];       // codebook @ W2^T + b2
__device__ float g_cb3[NCODE*PATCH];    // cb2 @ dec_w (spatially flipped)
__device__ float g_z[NPIX*CD];          // 64 MB
__device__ float g_znorm[NPIX];         // A = ||z||^2
__device__ float g_dmin[NPIX];
__device__ int   g_idx[NPIX];
__device__ float g_idxf_dummy[NPIX];
__device__ float g_part[256];

// ---------------- f32x2 helpers (Blackwell packed fp32) ----------------
// Per-lane rounding of fma.rn.f32x2 == scalar __fmaf_rn: each lane is an
// independent sequential ascending-k fused-FMA chain (matches Eigen gebp).
__device__ __forceinline__ uint64_t pack2(float a) {
    uint64_t r; uint32_t ai = __float_as_uint(a);
    asm("mov.b64 %0, {%1, %1};" : "=l"(r) : "r"(ai));
    return r;
}
__device__ __forceinline__ void ffma2(uint64_t& c, uint64_t a, uint64_t b) {
    asm("fma.rn.f32x2 %0, %1, %2, %3;" : "=l"(c) : "l"(a), "l"(b), "l"(c));
}
__device__ __forceinline__ void unpack2(uint64_t v, float& lo, float& hi) {
    uint32_t l, h;
    asm("mov.b64 {%0, %1}, %2;" : "=r"(l), "=r"(h) : "l"(v));
    lo = __uint_as_float(l); hi = __uint_as_float(h);
}

// ---------------- precompute: Wcomb[p][c] = sum_o We[o][p]*W1[c][o]; bcomb ----------------
__global__ void k_comb(const float* __restrict__ enc_w, const float* __restrict__ enc_b,
                       const float* __restrict__ w1, const float* __restrict__ b1)
{
    int c = threadIdx.x;
    int p = blockIdx.x;
    if (p < PATCH) {
        float s = 0.f;
        for (int o = 0; o < CD; ++o) s += enc_w[o*PATCH + p] * w1[c*CD + o];
        g_Wcomb[p*CD + c] = s;
    } else {
        float s = b1[c];
        for (int o = 0; o < CD; ++o) s += enc_b[o] * w1[c*CD + o];
        g_bcomb[c] = s;
    }
}

// C_k = ||c_k||^2 (order-insensitive at 1e-11 << grid; float4 ok)
__global__ void k_cnorm(const float* __restrict__ cb) {
    int k = blockIdx.x * blockDim.x + threadIdx.x;
    const float* r = cb + k*CD;
    float s = 0.f;
    for (int j = 0; j < CD; j += 4) {
        float4 v = *(const float4*)(r + j);
        s += v.x*v.x + v.y*v.y + v.z*v.z + v.w*v.w;
    }
    g_cnorm[k] = s;
}

// cb2[k][c] = sum_j codebook[k][j]*W2[c][j] + b2[c]  -- tiled NT GEMM 1024x256x256
__global__ void k_cb2(const float* __restrict__ A, const float* __restrict__ B,
                      const float* __restrict__ bias)
{
    __shared__ float As[64][17];
    __shared__ float Bs[16][65];
    int tx = threadIdx.x & 15, ty = threadIdx.x >> 4;
    int m0 = blockIdx.x * 64, n0 = blockIdx.y * 64;
    float acc[4][4] = {};
    for (int kt = 0; kt < 256; kt += 16) {
        {
            int f = threadIdx.x;
            int row = f >> 2, q = f & 3;
            float4 v = *(const float4*)&A[(m0+row)*256 + kt + q*4];
            As[row][q*4+0]=v.x; As[row][q*4+1]=v.y; As[row][q*4+2]=v.z; As[row][q*4+3]=v.w;
            float4 w = *(const float4*)&B[(n0+row)*256 + kt + q*4];
            Bs[q*4+0][row]=w.x; Bs[q*4+1][row]=w.y; Bs[q*4+2][row]=w.z; Bs[q*4+3][row]=w.w;
        }
        __syncthreads();
        #pragma unroll
        for (int kk = 0; kk < 16; ++kk) {
            float a[4], b[4];
            #pragma unroll
            for (int i = 0; i < 4; ++i) a[i] = As[ty*4+i][kk];
            #pragma unroll
            for (int j = 0; j < 4; ++j) b[j] = Bs[kk][tx*4+j];
            #pragma unroll
            for (int i = 0; i < 4; ++i)
                #pragma unroll
                for (int j = 0; j < 4; ++j) acc[i][j] += a[i]*b[j];
        }
        __syncthreads();
    }
    #pragma unroll
    for (int i = 0; i < 4; ++i)
        #pragma unroll
        for (int j = 0; j < 4; ++j)
            g_cb2[(m0+ty*4+i)*256 + n0+tx*4+j] = acc[i][j] + bias[n0+tx*4+j];
}

// cb3[k][q] with flip: conv_transpose(VALID, k=s=4, no kernel transpose) -> w[3-ki][3-kj]
__global__ void k_cb3(const float* __restrict__ dec_w) {
    __shared__ float row[CD];
    int k = blockIdx.x;
    for (int c = threadIdx.x; c < CD; c += 64) row[c] = g_cb2[k*CD + c];
    __syncthreads();
    int q = threadIdx.x;
    if (q < PATCH) {
        int o = q >> 4, r = q & 15, ki = r >> 2, kj = r & 3;
        int qf = o*16 + (3-ki)*4 + (3-kj);
        float s = 0.f;
        for (int c = 0; c < CD; ++c) s += row[c] * dec_w[c*PATCH + qf];
        g_cb3[k*PATCH + q] = s;
    }
}

// ---------------- z = patches @ Wcomb + bcomb : 65536 x 256, K=48 ----------------
__global__ void k_z(const float* __restrict__ x) {
    __shared__ float Ps[64][49];
    __shared__ float Ws[48][65];
    int tx = threadIdx.x & 15, ty = threadIdx.x >> 4;
    int m0 = blockIdx.x * 64, n0 = blockIdx.y * 64;
    for (int e = threadIdx.x; e < 64*48; e += 256) {
        int pix = e / 48, p = e - pix*48;
        int n = m0 + pix;
        int b = n >> 12, rem = n & 4095, i = rem >> 6, j = rem & 63;
        int cin = p >> 4, r = p & 15, ki = r >> 2, kj = r & 3;
        Ps[pix][p] = x[(((b*3 + cin) << 8) + (i*4 + ki))*256 + j*4 + kj];
    }
    for (int e = threadIdx.x; e < 48*16; e += 256) {
        int row = e >> 4, q = e & 15;
        float4 v = *(const float4*)&g_Wcomb[row*CD + n0 + q*4];
        Ws[row][q*4+0]=v.x; Ws[row][q*4+1]=v.y; Ws[row][q*4+2]=v.z; Ws[row][q*4+3]=v.w;
    }
    __syncthreads();
    float acc[4][4] = {};
    #pragma unroll 8
    for (int k = 0; k < 48; ++k) {
        float a[4], b[4];
        #pragma unroll
        for (int i = 0; i < 4; ++i) a[i] = Ps[ty*4+i][k];
        #pragma unroll
        for (int j = 0; j < 4; ++j) b[j] = Ws[k][tx*4+j];
        #pragma unroll
        for (int i = 0; i < 4; ++i)
            #pragma unroll
            for (int j = 0; j < 4; ++j) acc[i][j] += a[i]*b[j];
    }
    #pragma unroll
    for (int i = 0; i < 4; ++i)
        #pragma unroll
        for (int j = 0; j < 4; ++j)
            g_z[(m0+ty*4+i)*CD + n0+tx*4+j] = acc[i][j] + g_bcomb[n0+tx*4+j];
}

__global__ void k_znorm() {
    int row  = (blockIdx.x << 3) + (threadIdx.x >> 5);
    int lane = threadIdx.x & 31;
    const float* r = g_z + (size_t)row * CD;
    float4 a = *(const float4*)(r + lane*4);
    float4 b = *(const float4*)(r + 128 + lane*4);
    float s = a.x*a.x + a.y*a.y + a.z*a.z + a.w*a.w
            + b.x*b.x + b.y*b.y + b.z*b.z + b.w*b.w;
    #pragma unroll
    for (int off = 16; off; off >>= 1) s += __shfl_down_sync(0xffffffffu, s, off);
    if (!lane) g_znorm[row] = s;
}

// ---------------- distance GEMM + fused argmin (dominant kernel) ----------------
// M = z_n . c_k via sequential ascending-k fused-FMA chain (per f32x2 lane).
// Then REPLICATE the reference's quantized distance EXACTLY:
//     d = fl( fl( A - fl(2*M) ) + C )      (all fp32, round-to-nearest)
// and argmin with first-index tie-break. The 3e-5 quantization grid of d is
// what decides ~0.6% of rows; comparing unquantized scores caused the 78 flips.
__global__ void __launch_bounds__(256, 2) k_dist(const float* __restrict__ codebook,
                                                 float* __restrict__ idx_out)
{
    __shared__ __align__(16) float Zs[128][17];
    __shared__ __align__(16) float Cs[16][132];
    int m0 = blockIdx.x * 128;
    int tx = threadIdx.x & 15, ty = threadIdx.x >> 4;

    float Arow[8];
    #pragma unroll
    for (int ii = 0; ii < 8; ++ii) {
        int row = 32*(ii >> 1) + 2*ty + (ii & 1);
        Arow[ii] = g_znorm[m0 + row];
    }

    float best[8]; int bidx[8];
    #pragma unroll
    for (int i = 0; i < 8; ++i) { best[i] = CUDART_INF_F; bidx[i] = NCODE; }

    for (int nt = 0; nt < 8; ++nt) {
        uint64_t acc[8][4];
        #pragma unroll
        for (int i = 0; i < 8; ++i)
            #pragma unroll
            for (int j = 0; j < 4; ++j) acc[i][j] = 0ull;

        for (int kt = 0; kt < 256; kt += 16) {
            #pragma unroll
            for (int f = threadIdx.x; f < 512; f += 256) {
                int row = f >> 2, q = f & 3;
                float4 v = *(const float4*)&g_z[(m0+row)*256 + kt + q*4];
                Zs[row][q*4+0]=v.x; Zs[row][q*4+1]=v.y; Zs[row][q*4+2]=v.z; Zs[row][q*4+3]=v.w;
            }
            #pragma unroll
            for (int f = threadIdx.x; f < 512; f += 256) {
                int code = f >> 2, q = f & 3;
                float4 v = *(const float4*)&codebook[(nt*128+code)*256 + kt + q*4];
                Cs[q*4+0][code]=v.x; Cs[q*4+1][code]=v.y; Cs[q*4+2][code]=v.z; Cs[q*4+3][code]=v.w;
            }
            __syncthreads();
            #pragma unroll
            for (int kk = 0; kk < 16; ++kk) {
                uint64_t bv[4];
                #pragma unroll
                for (int jj = 0; jj < 4; ++jj)
                    bv[jj] = *reinterpret_cast<const uint64_t*>(&Cs[kk][32*jj + 2*tx]);
                #pragma unroll
                for (int ii = 0; ii < 8; ++ii) {
                    int row = 32*(ii >> 1) + 2*ty + (ii & 1);
                    uint64_t av = pack2(Zs[row][kk]);
                    #pragma unroll
                    for (int jj = 0; jj < 4; ++jj) ffma2(acc[ii][jj], av, bv[jj]);
                }
            }
            __syncthreads();
        }
        // epilogue: reference-exact d, running argmin (codes ascend per thread
        // across nt/jj => strict < keeps first index)
        #pragma unroll
        for (int jj = 0; jj < 4; ++jj) {
            int code = nt*128 + 32*jj + 2*tx;
            float C0 = g_cnorm[code], C1 = g_cnorm[code+1];
            #pragma unroll
            for (int ii = 0; ii < 8; ++ii) {
                float s0, s1; unpack2(acc[ii][jj], s0, s1);
                float t0 = __fadd_rn(Arow[ii], -__fadd_rn(s0, s0)); // A - 2M, rn
                float t1 = __fadd_rn(Arow[ii], -__fadd_rn(s1, s1));
                float d0 = __fadd_rn(t0, C0);
                float d1 = __fadd_rn(t1, C1);
                if (d0 < best[ii]) { best[ii] = d0; bidx[ii] = code; }
                if (d1 < best[ii]) { best[ii] = d1; bidx[ii] = code + 1; }
            }
        }
    }

    // cross-thread (tx) reduction via smem reuse; first-index on exact ties
    __syncthreads();
    float* redS = &Zs[0][0];
    int*   redI = (int*)&Cs[0][0];
    #pragma unroll
    for (int ii = 0; ii < 8; ++ii) {
        int row = 32*(ii >> 1) + 2*ty + (ii & 1);
        redS[row*16 + tx] = best[ii];
        redI[row*16 + tx] = bidx[ii];
    }
    __syncthreads();
    if (threadIdx.x < 128) {
        int row = threadIdx.x;
        float bs = redS[row*16]; int bi = redI[row*16];
        #pragma unroll
        for (int t = 1; t < 16; ++t) {
            float s = redS[row*16 + t]; int i2 = redI[row*16 + t];
            if (s < bs || (s == bs && i2 < bi)) { bs = s; bi = i2; }
        }
        int n = m0 + row;
        g_idx[n]  = bi;
        g_dmin[n] = bs;
        float* op = idx_out ? idx_out : g_idxf_dummy;
        op[n] = (float)bi;
    }
}

// ---------------- decode: scatter cb3[idx] into 4x4 output blocks ----------------
__global__ void k_decode(const float* __restrict__ dec_b, float* __restrict__ out) {
    int t = blockIdx.x * 256 + threadIdx.x;     // float4 index
    int v = t << 2;
    int j  = (v >> 2) & 63;
    int y  = (v >> 8) & 255;
    int bo = v >> 16;                            // b*3 + o
    int b  = bo / 3;
    int o  = bo - b*3;
    int i  = y >> 2, ki = y & 3;
    int n  = (b << 12) + (i << 6) + j;
    int id = g_idx[n];
    float4 w = *(const float4*)&g_cb3[id*PATCH + o*16 + (ki << 2)];
    float bb = dec_b[o];
    float4 r = make_float4(w.x + bb, w.y + bb, w.z + bb, w.w + bb);
    ((float4*)out)[t] = r;
}

// ---------------- deterministic loss reduction ----------------
__global__ void k_loss1() {
    __shared__ float sm[256];
    int t = threadIdx.x;
    sm[t] = g_dmin[blockIdx.x*256 + t];
    __syncthreads();
    for (int s = 128; s > 0; s >>= 1) { if (t < s) sm[t] += sm[t+s]; __syncthreads(); }
    if (!t) g_part[blockIdx.x] = sm[0];
}
__global__ void k_loss2(float* __restrict__ loss_out) {
    __shared__ float sm[256];
    int t = threadIdx.x;
    sm[t] = g_part[t];
    __syncthreads();
    for (int s = 128; s > 0; s >>= 1) { if (t < s) sm[t] += sm[t+s]; __syncthreads(); }
    if (!t) *loss_out = 1.25f * sm[0] / 16777216.0f;
}

// ---------------- launch ----------------
extern "C" void kernel_launch(void* const* d_in, const int* in_sizes, int n_in,
                              void* d_out, int out_size)
{
    const float* x     = (const float*)d_in[0];
    const float* enc_w = (const float*)d_in[1];
    const float* enc_b = (const float*)d_in[2];
    const float* w1    = (const float*)d_in[3];
    const float* b1    = (const float*)d_in[4];
    const float* cb    = (const float*)d_in[5];
    const float* w2    = (const float*)d_in[6];
    const float* b2    = (const float*)d_in[7];
    const float* dw    = (const float*)d_in[8];
    const float* db    = (const float*)d_in[9];
    float* out = (float*)d_out;

    k_comb <<<49, 256>>>(enc_w, enc_b, w1, b1);
    k_cnorm<<<4, 256>>>(cb);
    k_cb2  <<<dim3(16,4), 256>>>(cb, w2, b2);
    k_cb3  <<<1024, 64>>>(dw);
    k_z    <<<dim3(1024,4), 256>>>(x);
    k_znorm<<<8192, 256>>>();

    bool has_idx  = out_size >= 3145728 + 65536;
    bool has_loss = out_size >= 3145728 + 65536 + 1;
    k_dist <<<512, 256>>>(cb, has_idx ? out + 3145728 : nullptr);
    k_decode<<<3072, 256>>>(db, out);
    if (has_loss) {
        k_loss1<<<256, 256>>>();
        k_loss2<<<1, 256>>>(out + 3145728 + 65536);
    }
}